// round 16
// baseline (speedup 1.0000x reference)
#include <cuda_runtime.h>
#include <cuda_fp16.h>
#include <cstdint>

#define N_PIX 32768   // B*H*W
#define EMB   64
#define CH    128
#define NCODE 8192
#define HW    1024

// ---------------------------------------------------------------------------
// scratch (no allocations allowed)
// ---------------------------------------------------------------------------
__device__ float    g_ze[N_PIX * EMB];     // queries fp32, 8 MB
__device__ int      g_ind[N_PIX];
__device__ float    g_wn[NCODE];           // 0.5*||w||^2 fp32 (exact rescore)
__device__ __half   g_wnh[NCODE];          // 0.5*||w||^2 f16 (coarse scan)
__device__ __half   g_cbh[NCODE * EMB];    // codebook f16 row-major, 1 MB
__device__ int      g_wmaxi = 0;
__device__ float    g_loss;

__device__ __forceinline__ uint32_t smem_u32(const void* p) {
    uint32_t a;
    asm("{ .reg .u64 t; cvta.to.shared.u64 t, %1; cvt.u32.u64 %0, t; }"
        : "=r"(a) : "l"(p));
    return a;
}
__device__ __forceinline__ uint32_t f2h2(float lo, float hi) {
    uint32_t r;
    asm("cvt.rn.f16x2.f32 %0, %1, %2;" : "=r"(r) : "f"(hi), "f"(lo));
    return r;
}
__device__ __forceinline__ float2 h2f2(uint32_t h) {
    __half2 hh = *reinterpret_cast<__half2*>(&h);
    return __half22float2(hh);
}
__device__ __forceinline__ uint32_t hsub2u(uint32_t a, uint32_t b) {
    uint32_t r;
    asm("sub.f16x2 %0, %1, %2;" : "=r"(r) : "r"(a), "r"(b));
    return r;
}
__device__ __forceinline__ uint32_t hmax2u(uint32_t a, uint32_t b) {
    uint32_t r;
    asm("max.f16x2 %0, %1, %2;" : "=r"(r) : "r"(a), "r"(b));
    return r;
}
// f16-accumulator MMA: D(f16x2 x2) = A(f16 x4) * B(f16 x2) + D
__device__ __forceinline__ void mma_f16(uint32_t* d, const uint32_t* a,
                                        uint32_t b0, uint32_t b1) {
    asm volatile(
        "mma.sync.aligned.m16n8k16.row.col.f16.f16.f16.f16 "
        "{%0,%1},{%2,%3,%4,%5},{%6,%7},{%0,%1};"
        : "+r"(d[0]), "+r"(d[1])
        : "r"(a[0]), "r"(a[1]), "r"(a[2]), "r"(a[3]), "r"(b0), "r"(b1));
}

// ---------------------------------------------------------------------------
// K0: half-norms (fp32 + f16), f16 codebook, max norm, zero loss
// ---------------------------------------------------------------------------
__global__ void k_wn(const float* __restrict__ ew) {
    int j = blockIdx.x * blockDim.x + threadIdx.x;
    const float4* p = (const float4*)(ew + (size_t)j * EMB);
    uint4 packed[8];
    float s = 0.f;
#pragma unroll
    for (int i = 0; i < 8; ++i) {
        float4 a = p[2 * i], b = p[2 * i + 1];
        s += a.x * a.x + a.y * a.y + a.z * a.z + a.w * a.w;
        s += b.x * b.x + b.y * b.y + b.z * b.z + b.w * b.w;
        packed[i] = make_uint4(f2h2(a.x, a.y), f2h2(a.z, a.w),
                               f2h2(b.x, b.y), f2h2(b.z, b.w));
    }
    uint4* dst = (uint4*)(g_cbh + (size_t)j * EMB);
#pragma unroll
    for (int i = 0; i < 8; ++i) dst[i] = packed[i];
    g_wn[j] = 0.5f * s;
    g_wnh[j] = __float2half(0.5f * s);
    atomicMax(&g_wmaxi, __float_as_int(sqrtf(s)));
    if (j == 0) g_loss = 0.f;
}

// ---------------------------------------------------------------------------
// K1: projection -> g_ze fp32
// ---------------------------------------------------------------------------
__global__ __launch_bounds__(256) void k_proj(const float* __restrict__ z,
                                              const float* __restrict__ pw,
                                              const float* __restrict__ pb) {
    __shared__ float projs[EMB][CH + 4];
    __shared__ float zs[CH][18];
    int tid = threadIdx.x;
    int pbase = blockIdx.x * 16;
    for (int i = tid; i < EMB * CH / 4; i += 256) {
        int e = i >> 5;
        int c4 = (i & 31) << 2;
        float4 v = ((const float4*)pw)[i];
        projs[e][c4] = v.x; projs[e][c4 + 1] = v.y;
        projs[e][c4 + 2] = v.z; projs[e][c4 + 3] = v.w;
    }
    for (int i = tid; i < CH * 16; i += 256) {
        int c = i >> 4, p = i & 15, n = pbase + p;
        zs[c][p] = z[(n >> 10) * (CH * HW) + c * HW + (n & 1023)];
    }
    __syncthreads();
    int e = tid & 63, pg = tid >> 6;
    float bias = pb[e];
    for (int p = pg; p < 16; p += 4) {
        float acc = bias;
#pragma unroll
        for (int c = 0; c < CH; c += 4) {
            float4 w = *(const float4*)&projs[e][c];
            acc += w.x * zs[c][p];     acc += w.y * zs[c + 1][p];
            acc += w.z * zs[c + 2][p]; acc += w.w * zs[c + 3][p];
        }
        g_ze[(pbase + p) * EMB + e] = acc;
    }
}

// ---------------------------------------------------------------------------
// K2: f16-acc mma.sync coarse argmax + exact fp32 rescue.
// 8 warps = 4 warpm (32q) x 2 warpn (64c). Packed f16x2 epilogue.
// 3-stage cp.async; 2 CTAs/SM.
// ---------------------------------------------------------------------------
#define NT  64             // 8192 / 128 code tiles
#define CAP 32
#define SM_B   0u          // 3 x 16384 = 49152
#define SM_WN  49152u      // 8192 f16 = 16384
#define SM_CI  65536u      // 128*CAP i32 = 16384
#define SM_CNT 81920u      // 128 i32
#define SMEM_TOTAL 82432

__device__ __forceinline__ float exact_score(const float* __restrict__ qv,
                                             const float* __restrict__ ew, int idx) {
    const float4* w = (const float4*)(ew + (size_t)idx * EMB);
    float s = 0.f;
#pragma unroll
    for (int i = 0; i < 16; ++i) {
        float4 v = w[i];
        s = fmaf(qv[4 * i], v.x, s);
        s = fmaf(qv[4 * i + 1], v.y, s);
        s = fmaf(qv[4 * i + 2], v.z, s);
        s = fmaf(qv[4 * i + 3], v.w, s);
    }
    return s - __ldg(&g_wn[idx]);
}

__device__ __forceinline__ void load_btile(uint32_t dstbase, const char* srcbase,
                                           int tid) {
#pragma unroll
    for (int r = 0; r < 4; ++r) {
        int i = tid + 256 * r;          // chunk id 0..1023
        int n = i >> 3, c = i & 7;      // code row, 16B chunk
        uint32_t dst = dstbase + n * 128 + (((uint32_t)(c ^ (n & 7))) << 4);
        const char* src = srcbase + n * 128 + c * 16;
        asm volatile("cp.async.cg.shared.global [%0], [%1], 16;"
                     :: "r"(dst), "l"(src) : "memory");
    }
    asm volatile("cp.async.commit_group;" ::: "memory");
}

__global__ __launch_bounds__(256, 2) void k_argmax_mma(const float* __restrict__ ew) {
    extern __shared__ char smc[];
    uint32_t* wnh2 = (uint32_t*)(smc + SM_WN);   // f16x2 pairs [4096]
    int*      cidx = (int*)(smc + SM_CI);
    int*      cnt  = (int*)(smc + SM_CNT);
    uint32_t sb = smem_u32(smc);

    int tid = threadIdx.x;
    int wid = tid >> 5, lane = tid & 31;
    int warpm = wid & 3, warpn = wid >> 2;
    int g = lane >> 2, tq = lane & 3;
    int qb = blockIdx.x * 128;

    if (tid < 128) cnt[tid] = 0;
    for (int i = tid; i < NCODE * 2 / 16; i += 256)     // 16 KB as uint4
        ((uint4*)wnh2)[i] = ((const uint4*)g_wnh)[i];

    // A fragments: 2 query sets x 16 rows, f16; plus ||x||^2 partials
    uint32_t afr[2][4][4];
    float sum[2][2] = {{0.f, 0.f}, {0.f, 0.f}};
    int qw = qb + warpm * 32;
#pragma unroll
    for (int s = 0; s < 2; ++s) {
        const float* r0 = g_ze + (size_t)(qw + s * 16 + g) * EMB;
        const float* r1 = r0 + 8 * EMB;
#pragma unroll
        for (int ks = 0; ks < 4; ++ks) {
            float2 v;
            v = *(const float2*)(r0 + ks * 16 + 2 * tq);
            afr[s][ks][0] = f2h2(v.x, v.y); sum[s][0] += v.x * v.x + v.y * v.y;
            v = *(const float2*)(r1 + ks * 16 + 2 * tq);
            afr[s][ks][1] = f2h2(v.x, v.y); sum[s][1] += v.x * v.x + v.y * v.y;
            v = *(const float2*)(r0 + ks * 16 + 2 * tq + 8);
            afr[s][ks][2] = f2h2(v.x, v.y); sum[s][0] += v.x * v.x + v.y * v.y;
            v = *(const float2*)(r1 + ks * 16 + 2 * tq + 8);
            afr[s][ks][3] = f2h2(v.x, v.y); sum[s][1] += v.x * v.x + v.y * v.y;
        }
    }
    float wmax = __int_as_float(__ldg(&g_wmaxi));
    float eps[2][2], thr[2][2];
#pragma unroll
    for (int s = 0; s < 2; ++s)
#pragma unroll
        for (int h = 0; h < 2; ++h) {
            float t2 = sum[s][h];
            t2 += __shfl_xor_sync(0xffffffffu, t2, 1);
            t2 += __shfl_xor_sync(0xffffffffu, t2, 2);
            eps[s][h] = sqrtf(t2) * wmax * (1.0f / 64.0f) + 0.1f;
            thr[s][h] = -3.0e38f;
        }

    // ldmatrix.x4 addressing (rows within warp's 64-code half)
    int laneRow = lane & 7;
    int q4 = (lane >> 3) & 3;
    uint32_t off0 = (uint32_t)laneRow * 128u
                  + (((uint32_t)(q4 ^ laneRow)) << 4);        // k chunks 0-3
    uint32_t off1 = (uint32_t)laneRow * 128u
                  + (((uint32_t)((4 + q4) ^ laneRow)) << 4);  // k chunks 4-7
    uint32_t hoff = (uint32_t)warpn * 8192u;                  // code-half offset

    // prologue: tiles 0,1
    load_btile(sb + SM_B, (const char*)g_cbh, tid);
    load_btile(sb + SM_B + 16384u, (const char*)g_cbh + 16384, tid);

    for (int t = 0; t < NT; ++t) {
        if (t + 2 < NT) {
            load_btile(sb + SM_B + (uint32_t)((t + 2) % 3) * 16384u,
                       (const char*)g_cbh + (size_t)(t + 2) * 16384, tid);
            asm volatile("cp.async.wait_group 2;" ::: "memory");
        } else if (t + 1 < NT) {
            asm volatile("cp.async.wait_group 1;" ::: "memory");
        } else {
            asm volatile("cp.async.wait_group 0;" ::: "memory");
        }
        __syncthreads();

        // acc = packed f16x2 scores: [set][j][row-half], 32 regs
        uint32_t acc[2][8][2];
#pragma unroll
        for (int s = 0; s < 2; ++s)
#pragma unroll
            for (int j = 0; j < 8; ++j) { acc[s][j][0] = 0u; acc[s][j][1] = 0u; }

        uint32_t bbase = sb + SM_B + (uint32_t)(t % 3) * 16384u + hoff;
#pragma unroll
        for (int j = 0; j < 8; ++j) {
            uint32_t jb = bbase + (uint32_t)j * 1024u;
            uint32_t b0, b1, b2, b3, b4, b5, b6, b7;
            asm volatile("ldmatrix.sync.aligned.m8n8.x4.shared.b16 {%0,%1,%2,%3}, [%4];"
                         : "=r"(b0), "=r"(b1), "=r"(b2), "=r"(b3)
                         : "r"(jb + off0));
            asm volatile("ldmatrix.sync.aligned.m8n8.x4.shared.b16 {%0,%1,%2,%3}, [%4];"
                         : "=r"(b4), "=r"(b5), "=r"(b6), "=r"(b7)
                         : "r"(jb + off1));
#pragma unroll
            for (int s = 0; s < 2; ++s) {
                mma_f16(acc[s][j], afr[s][0], b0, b1);
                mma_f16(acc[s][j], afr[s][1], b2, b3);
                mma_f16(acc[s][j], afr[s][2], b4, b5);
                mma_f16(acc[s][j], afr[s][3], b6, b7);
            }
        }

        // packed score: subtract 0.5||w||^2 (f16x2)
#pragma unroll
        for (int j = 0; j < 8; ++j) {
            uint32_t wn2 = wnh2[t * 64 + warpn * 32 + j * 4 + tq];
#pragma unroll
            for (int s = 0; s < 2; ++s) {
                acc[s][j][0] = hsub2u(acc[s][j][0], wn2);
                acc[s][j][1] = hsub2u(acc[s][j][1], wn2);
            }
        }

        // pass 1: packed tile max -> thresholds; ballot skip
        bool any = false;
#pragma unroll
        for (int s = 0; s < 2; ++s)
#pragma unroll
            for (int h = 0; h < 2; ++h) {
                uint32_t m2 = acc[s][0][h];
#pragma unroll
                for (int j = 1; j < 8; ++j) m2 = hmax2u(m2, acc[s][j][h]);
                float2 f = h2f2(m2);
                float m = fmaxf(f.x, f.y);
                m = fmaxf(m, __shfl_xor_sync(0xffffffffu, m, 1));
                m = fmaxf(m, __shfl_xor_sync(0xffffffffu, m, 2));
                any |= (m > thr[s][h]);
                thr[s][h] = fmaxf(thr[s][h], m - eps[s][h]);
            }
        if (!__ballot_sync(0xffffffffu, any)) {
            __syncthreads();
            continue;
        }

        // pass 2: append candidate indices
#pragma unroll
        for (int j = 0; j < 8; ++j) {
            int col0 = t * 128 + warpn * 64 + j * 8 + 2 * tq;
#pragma unroll
            for (int s = 0; s < 2; ++s) {
                int qlb = warpm * 32 + s * 16 + g;
#pragma unroll
                for (int h = 0; h < 2; ++h) {
                    float2 f = h2f2(acc[s][j][h]);
                    int ql = qlb + 8 * h;
                    if (f.x > thr[s][h]) {
                        int p = atomicAdd(&cnt[ql], 1);
                        if (p < CAP) cidx[ql * CAP + p] = col0;
                    }
                    if (f.y > thr[s][h]) {
                        int p = atomicAdd(&cnt[ql], 1);
                        if (p < CAP) cidx[ql * CAP + p] = col0 + 1;
                    }
                }
            }
        }
        __syncthreads();
    }

    // final: exact fp32 rescore of all candidates (order-independent)
    if (tid < 128) {
        int q = tid, n = qb + q;
        int c = cnt[q];
        float qv[64];
        const float4* qp = (const float4*)(g_ze + (size_t)n * EMB);
#pragma unroll
        for (int i = 0; i < 16; ++i) {
            float4 v = qp[i];
            qv[4 * i] = v.x; qv[4 * i + 1] = v.y;
            qv[4 * i + 2] = v.z; qv[4 * i + 3] = v.w;
        }
        float bv = -3.0e38f;
        int bi = 0x7fffffff;
        if (c > CAP) {  // overflow fallback: exact full scan (should be ~never)
            for (int id = 0; id < NCODE; ++id) {
                float s = exact_score(qv, ew, id);
                if (s > bv) { bv = s; bi = id; }
            }
        } else {
            for (int k = 0; k < c; ++k) {
                int id = cidx[q * CAP + k];
                float s = exact_score(qv, ew, id);
                if (s > bv || (s == bv && id < bi)) { bv = s; bi = id; }
            }
        }
        g_ind[n] = bi;
    }
}

// ---------------------------------------------------------------------------
// K3: gather + outputs + loss (coalesced two-phase)
// ---------------------------------------------------------------------------
__global__ __launch_bounds__(256) void k_gather(const float* __restrict__ ew,
                                                float* __restrict__ out,
                                                int full_out) {
    __shared__ float vt[64][EMB + 1];
    int tid = threadIdx.x;
    int blk = blockIdx.x;

    int e = tid & 63, pg = tid >> 6;
    float s = 0.f;
    for (int pp = pg; pp < 64; pp += 4) {
        int n = blk * 64 + pp;
        int idx = g_ind[n];
        float v = ew[(size_t)idx * EMB + e];
        vt[pp][e] = v;
        float d = v - g_ze[(size_t)n * EMB + e];
        s += d * d;
        if (full_out) out[N_PIX * EMB + (size_t)n * EMB + e] = v;
    }
    if (full_out && tid < 64) {
        int n = blk * 64 + tid;
        out[2 * N_PIX * EMB + 1 + n] = (float)g_ind[n];
    }
    __syncthreads();

    int p = tid & 63, eg = tid >> 6;
    int n = blk * 64 + p;
    int b = n >> 10, hw = n & 1023;
    float* outp = out + (size_t)b * (EMB * HW) + hw;
#pragma unroll
    for (int ee = 0; ee < EMB / 4; ++ee)
        outp[(size_t)(eg + 4 * ee) * HW] = vt[p][eg + 4 * ee];

#pragma unroll
    for (int off = 16; off > 0; off >>= 1)
        s += __shfl_down_sync(0xffffffffu, s, off);
    __shared__ float ps[8];
    if ((tid & 31) == 0) ps[tid >> 5] = s;
    __syncthreads();
    if (tid < 8) {
        s = ps[tid];
#pragma unroll
        for (int off = 4; off > 0; off >>= 1)
            s += __shfl_down_sync(0xffu, s, off);
        if (tid == 0) atomicAdd(&g_loss, s);
    }
}

__global__ void k_fin(float* __restrict__ out, int full_out) {
    if (full_out)
        out[2 * N_PIX * EMB] = 12.5f * g_loss / (float)(N_PIX * EMB);
}

// ---------------------------------------------------------------------------
extern "C" void kernel_launch(void* const* d_in, const int* in_sizes, int n_in,
                              void* d_out, int out_size) {
    const float* z  = (const float*)d_in[0];
    const float* pw = (const float*)d_in[1];
    const float* pb = (const float*)d_in[2];
    const float* ew = (const float*)d_in[3];
    float* out = (float*)d_out;

    int full_out = (out_size >= 2 * N_PIX * EMB + 1 + N_PIX) ? 1 : 0;

    cudaFuncSetAttribute(k_argmax_mma, cudaFuncAttributeMaxDynamicSharedMemorySize,
                         SMEM_TOTAL);

    k_wn<<<NCODE / 256, 256>>>(ew);
    k_proj<<<N_PIX / 16, 256>>>(z, pw, pb);
    k_argmax_mma<<<N_PIX / 128, 256, SMEM_TOTAL>>>(ew);
    k_gather<<<N_PIX / 64, 256>>>(ew, out, full_out);
    k_fin<<<1, 1>>>(out, full_out);
}

// round 17
// speedup vs baseline: 12.2823x; 12.2823x over previous
#include <cuda_runtime.h>
#include <cuda_bf16.h>
#include <cstdint>

#define N_PIX 32768   // B*H*W
#define EMB   64
#define CH    128
#define NCODE 8192
#define HW    1024

// ---------------------------------------------------------------------------
// scratch (no allocations allowed)
// ---------------------------------------------------------------------------
__device__ float         g_ze[N_PIX * EMB];     // queries fp32, 8 MB
__device__ int           g_ind[N_PIX];
__device__ float         g_wn[NCODE];           // 0.5*||w||^2 fp32
__device__ __nv_bfloat16 g_cb[NCODE * EMB];     // codebook bf16 row-major
__device__ int           g_wmaxi = 0;
__device__ float         g_loss;

__device__ __forceinline__ uint32_t smem_u32(const void* p) {
    uint32_t a;
    asm("{ .reg .u64 t; cvta.to.shared.u64 t, %1; cvt.u32.u64 %0, t; }"
        : "=r"(a) : "l"(p));
    return a;
}
__device__ __forceinline__ uint32_t bf2(float lo, float hi) {
    uint32_t r;
    asm("cvt.rn.bf16x2.f32 %0, %1, %2;" : "=r"(r) : "f"(hi), "f"(lo));
    return r;
}
__device__ __forceinline__ void mma_bf16(float* c, const uint32_t* a,
                                         uint32_t b0, uint32_t b1) {
    asm volatile(
        "mma.sync.aligned.m16n8k16.row.col.f32.bf16.bf16.f32 "
        "{%0,%1,%2,%3},{%4,%5,%6,%7},{%8,%9},{%0,%1,%2,%3};"
        : "+f"(c[0]), "+f"(c[1]), "+f"(c[2]), "+f"(c[3])
        : "r"(a[0]), "r"(a[1]), "r"(a[2]), "r"(a[3]), "r"(b0), "r"(b1));
}

// ---------------------------------------------------------------------------
// K0: code half-norms fp32, bf16 codebook, max norm, zero loss
// ---------------------------------------------------------------------------
__global__ void k_wn(const float* __restrict__ ew) {
    int j = blockIdx.x * blockDim.x + threadIdx.x;
    const float4* p = (const float4*)(ew + (size_t)j * EMB);
    uint4 packed[8];
    float s = 0.f;
#pragma unroll
    for (int i = 0; i < 8; ++i) {
        float4 a = p[2 * i], b = p[2 * i + 1];
        s += a.x * a.x + a.y * a.y + a.z * a.z + a.w * a.w;
        s += b.x * b.x + b.y * b.y + b.z * b.z + b.w * b.w;
        packed[i] = make_uint4(bf2(a.x, a.y), bf2(a.z, a.w),
                               bf2(b.x, b.y), bf2(b.z, b.w));
    }
    uint4* dst = (uint4*)(g_cb + (size_t)j * EMB);
#pragma unroll
    for (int i = 0; i < 8; ++i) dst[i] = packed[i];
    g_wn[j] = 0.5f * s;
    atomicMax(&g_wmaxi, __float_as_int(sqrtf(s)));
    if (j == 0) g_loss = 0.f;
}

// ---------------------------------------------------------------------------
// K1: projection -> g_ze fp32
// ---------------------------------------------------------------------------
__global__ __launch_bounds__(256) void k_proj(const float* __restrict__ z,
                                              const float* __restrict__ pw,
                                              const float* __restrict__ pb) {
    __shared__ float projs[EMB][CH + 4];
    __shared__ float zs[CH][18];
    int tid = threadIdx.x;
    int pbase = blockIdx.x * 16;
    for (int i = tid; i < EMB * CH / 4; i += 256) {
        int e = i >> 5;
        int c4 = (i & 31) << 2;
        float4 v = ((const float4*)pw)[i];
        projs[e][c4] = v.x; projs[e][c4 + 1] = v.y;
        projs[e][c4 + 2] = v.z; projs[e][c4 + 3] = v.w;
    }
    for (int i = tid; i < CH * 16; i += 256) {
        int c = i >> 4, p = i & 15, n = pbase + p;
        zs[c][p] = z[(n >> 10) * (CH * HW) + c * HW + (n & 1023)];
    }
    __syncthreads();
    int e = tid & 63, pg = tid >> 6;
    float bias = pb[e];
    for (int p = pg; p < 16; p += 4) {
        float acc = bias;
#pragma unroll
        for (int c = 0; c < CH; c += 4) {
            float4 w = *(const float4*)&projs[e][c];
            acc += w.x * zs[c][p];     acc += w.y * zs[c + 1][p];
            acc += w.z * zs[c + 2][p]; acc += w.w * zs[c + 3][p];
        }
        g_ze[(pbase + p) * EMB + e] = acc;
    }
}

// ---------------------------------------------------------------------------
// K2: mma.sync bf16/f32-acc coarse argmax + exact fp32 rescue.
// 8 warps x (16q x 128c sub-tile); 256-code tiles (2 sub-tiles), 3-stage
// cp.async, ONE syncthreads per tile; wn via __ldg; 2 CTAs/SM.
// ---------------------------------------------------------------------------
#define NT  32             // 8192 / 256 code tiles
#define CAP 28
#define SM_B   0u          // 3 x 32768 = 98304
#define SM_CI  98304u      // 128*CAP i32 = 14336
#define SM_CNT 112640u     // 128 i32
#define SMEM_TOTAL 113152

__device__ __forceinline__ float exact_score(const float* __restrict__ qv,
                                             const float* __restrict__ ew, int idx) {
    const float4* w = (const float4*)(ew + (size_t)idx * EMB);
    float s = 0.f;
#pragma unroll
    for (int i = 0; i < 16; ++i) {
        float4 v = w[i];
        s = fmaf(qv[4 * i], v.x, s);
        s = fmaf(qv[4 * i + 1], v.y, s);
        s = fmaf(qv[4 * i + 2], v.z, s);
        s = fmaf(qv[4 * i + 3], v.w, s);
    }
    return s - __ldg(&g_wn[idx]);
}

// 32 KB tile: 2048 16B chunks, 8 per thread
__device__ __forceinline__ void load_btile(uint32_t dstbase, const char* srcbase,
                                           int tid) {
#pragma unroll
    for (int r = 0; r < 8; ++r) {
        int i = tid + 256 * r;          // chunk id 0..2047
        int n = i >> 3, c = i & 7;      // code row (0..255), 16B chunk
        uint32_t dst = dstbase + n * 128 + (((uint32_t)(c ^ (n & 7))) << 4);
        const char* src = srcbase + n * 128 + c * 16;
        asm volatile("cp.async.cg.shared.global [%0], [%1], 16;"
                     :: "r"(dst), "l"(src) : "memory");
    }
    asm volatile("cp.async.commit_group;" ::: "memory");
}

__global__ __launch_bounds__(256, 2) void k_argmax_mma(const float* __restrict__ ew) {
    extern __shared__ char smc[];
    int* cidx = (int*)(smc + SM_CI);
    int* cnt  = (int*)(smc + SM_CNT);
    uint32_t sb = smem_u32(smc);

    int tid = threadIdx.x;
    int wid = tid >> 5, lane = tid & 31;
    int g = lane >> 2, tq = lane & 3;
    int qb = blockIdx.x * 128;

    if (tid < 128) cnt[tid] = 0;

    // A fragments (16 query rows per warp) + ||x||^2 partials for eps
    uint32_t afr[4][4];
    float sum0 = 0.f, sum1 = 0.f;
    {
        const float* r0 = g_ze + (size_t)(qb + wid * 16 + g) * EMB;
        const float* r1 = r0 + 8 * EMB;
#pragma unroll
        for (int ks = 0; ks < 4; ++ks) {
            float2 v;
            v = *(const float2*)(r0 + ks * 16 + 2 * tq);
            afr[ks][0] = bf2(v.x, v.y); sum0 += v.x * v.x + v.y * v.y;
            v = *(const float2*)(r1 + ks * 16 + 2 * tq);
            afr[ks][1] = bf2(v.x, v.y); sum1 += v.x * v.x + v.y * v.y;
            v = *(const float2*)(r0 + ks * 16 + 2 * tq + 8);
            afr[ks][2] = bf2(v.x, v.y); sum0 += v.x * v.x + v.y * v.y;
            v = *(const float2*)(r1 + ks * 16 + 2 * tq + 8);
            afr[ks][3] = bf2(v.x, v.y); sum1 += v.x * v.x + v.y * v.y;
        }
    }
    sum0 += __shfl_xor_sync(0xffffffffu, sum0, 1);
    sum0 += __shfl_xor_sync(0xffffffffu, sum0, 2);
    sum1 += __shfl_xor_sync(0xffffffffu, sum1, 1);
    sum1 += __shfl_xor_sync(0xffffffffu, sum1, 2);
    float wmax = __int_as_float(__ldg(&g_wmaxi));
    float eps0 = sqrtf(sum0) * wmax * (1.0f / 64.0f) + 0.02f;
    float eps1 = sqrtf(sum1) * wmax * (1.0f / 64.0f) + 0.02f;
    float thr0 = -3.0e38f, thr1 = -3.0e38f;

    // ldmatrix.x4 addressing (within a 128-code sub-tile)
    int laneRow = lane & 7;
    int q4 = (lane >> 3) & 3;
    uint32_t off0 = (uint32_t)laneRow * 128u
                  + (((uint32_t)(q4 ^ laneRow)) << 4);        // k chunks 0-3
    uint32_t off1 = (uint32_t)laneRow * 128u
                  + (((uint32_t)((4 + q4) ^ laneRow)) << 4);  // k chunks 4-7

    // prologue: tiles 0,1
    load_btile(sb + SM_B, (const char*)g_cb, tid);
    load_btile(sb + SM_B + 32768u, (const char*)g_cb + 32768, tid);

    int ql0 = wid * 16 + g, ql1 = ql0 + 8;

    for (int t = 0; t < NT; ++t) {
        if (t + 1 < NT) {
            asm volatile("cp.async.wait_group 1;" ::: "memory");
        } else {
            asm volatile("cp.async.wait_group 0;" ::: "memory");
        }
        __syncthreads();   // all warps done with tile t-1; tile t resident
        if (t + 2 < NT)    // safe: buffer (t+2)%3 == (t-1)%3, finished above
            load_btile(sb + SM_B + (uint32_t)((t + 2) % 3) * 32768u,
                       (const char*)g_cb + (size_t)(t + 2) * 32768, tid);

        uint32_t tb = sb + SM_B + (uint32_t)(t % 3) * 32768u;

#pragma unroll
        for (int half = 0; half < 2; ++half) {
            float acc[16][4];
#pragma unroll
            for (int j = 0; j < 16; ++j)
#pragma unroll
                for (int k = 0; k < 4; ++k) acc[j][k] = 0.f;

            uint32_t bbase = tb + (uint32_t)half * 16384u;
#pragma unroll
            for (int j = 0; j < 16; ++j) {
                uint32_t jb = bbase + (uint32_t)j * 1024u;
                uint32_t b0, b1, b2, b3;
                asm volatile(
                    "ldmatrix.sync.aligned.m8n8.x4.shared.b16 {%0,%1,%2,%3}, [%4];"
                    : "=r"(b0), "=r"(b1), "=r"(b2), "=r"(b3) : "r"(jb + off0));
                mma_bf16(acc[j], afr[0], b0, b1);
                mma_bf16(acc[j], afr[1], b2, b3);
                asm volatile(
                    "ldmatrix.sync.aligned.m8n8.x4.shared.b16 {%0,%1,%2,%3}, [%4];"
                    : "=r"(b0), "=r"(b1), "=r"(b2), "=r"(b3) : "r"(jb + off1));
                mma_bf16(acc[j], afr[2], b0, b1);
                mma_bf16(acc[j], afr[3], b2, b3);
            }

            int cb0 = t * 256 + half * 128;
            // scores in place: subtract 0.5||w||^2 (wn from L1 via __ldg)
#pragma unroll
            for (int j = 0; j < 16; ++j) {
                float2 wn2 = __ldg((const float2*)&g_wn[cb0 + j * 8 + 2 * tq]);
                acc[j][0] -= wn2.x; acc[j][1] -= wn2.y;
                acc[j][2] -= wn2.x; acc[j][3] -= wn2.y;
            }

            // pass 1: sub-tile max -> threshold (quad share; single owner)
            float thr0_old = thr0, thr1_old = thr1;
            {
                float m0 = -3.0e38f, m1 = -3.0e38f;
#pragma unroll
                for (int j = 0; j < 16; ++j) {
                    m0 = fmaxf(m0, fmaxf(acc[j][0], acc[j][1]));
                    m1 = fmaxf(m1, fmaxf(acc[j][2], acc[j][3]));
                }
                m0 = fmaxf(m0, __shfl_xor_sync(0xffffffffu, m0, 1));
                m0 = fmaxf(m0, __shfl_xor_sync(0xffffffffu, m0, 2));
                m1 = fmaxf(m1, __shfl_xor_sync(0xffffffffu, m1, 1));
                m1 = fmaxf(m1, __shfl_xor_sync(0xffffffffu, m1, 2));
                thr0 = fmaxf(thr0, m0 - eps0);
                thr1 = fmaxf(thr1, m1 - eps1);
                if (!__ballot_sync(0xffffffffu,
                                   (m0 > thr0_old) || (m1 > thr1_old)))
                    continue;   // no candidate possible in this sub-tile
            }

            // pass 2: append candidate indices only
#pragma unroll
            for (int j = 0; j < 16; ++j) {
                int col0 = cb0 + j * 8 + 2 * tq;
                if (acc[j][0] > thr0) {
                    int p = atomicAdd(&cnt[ql0], 1);
                    if (p < CAP) cidx[ql0 * CAP + p] = col0;
                }
                if (acc[j][1] > thr0) {
                    int p = atomicAdd(&cnt[ql0], 1);
                    if (p < CAP) cidx[ql0 * CAP + p] = col0 + 1;
                }
                if (acc[j][2] > thr1) {
                    int p = atomicAdd(&cnt[ql1], 1);
                    if (p < CAP) cidx[ql1 * CAP + p] = col0;
                }
                if (acc[j][3] > thr1) {
                    int p = atomicAdd(&cnt[ql1], 1);
                    if (p < CAP) cidx[ql1 * CAP + p] = col0 + 1;
                }
            }
        }
    }
    __syncthreads();

    // final: exact fp32 rescore of all candidates (order-independent)
    if (tid < 128) {
        int q = tid, n = qb + q;
        int c = cnt[q];
        float qv[64];
        const float4* qp = (const float4*)(g_ze + (size_t)n * EMB);
#pragma unroll
        for (int i = 0; i < 16; ++i) {
            float4 v = qp[i];
            qv[4 * i] = v.x; qv[4 * i + 1] = v.y;
            qv[4 * i + 2] = v.z; qv[4 * i + 3] = v.w;
        }
        float bv = -3.0e38f;
        int bi = 0x7fffffff;
        if (c > CAP) {  // overflow fallback: exact full scan (should be ~never)
            for (int id = 0; id < NCODE; ++id) {
                float s = exact_score(qv, ew, id);
                if (s > bv) { bv = s; bi = id; }
            }
        } else {
            for (int k = 0; k < c; ++k) {
                int id = cidx[q * CAP + k];
                float s = exact_score(qv, ew, id);
                if (s > bv || (s == bv && id < bi)) { bv = s; bi = id; }
            }
        }
        g_ind[n] = bi;
    }
}

// ---------------------------------------------------------------------------
// K3: gather + outputs + loss (coalesced two-phase)
// ---------------------------------------------------------------------------
__global__ __launch_bounds__(256) void k_gather(const float* __restrict__ ew,
                                                float* __restrict__ out,
                                                int full_out) {
    __shared__ float vt[64][EMB + 1];
    int tid = threadIdx.x;
    int blk = blockIdx.x;

    int e = tid & 63, pg = tid >> 6;
    float s = 0.f;
    for (int pp = pg; pp < 64; pp += 4) {
        int n = blk * 64 + pp;
        int idx = g_ind[n];
        float v = ew[(size_t)idx * EMB + e];
        vt[pp][e] = v;
        float d = v - g_ze[(size_t)n * EMB + e];
        s += d * d;
        if (full_out) out[N_PIX * EMB + (size_t)n * EMB + e] = v;
    }
    if (full_out && tid < 64) {
        int n = blk * 64 + tid;
        out[2 * N_PIX * EMB + 1 + n] = (float)g_ind[n];
    }
    __syncthreads();

    int p = tid & 63, eg = tid >> 6;
    int n = blk * 64 + p;
    int b = n >> 10, hw = n & 1023;
    float* outp = out + (size_t)b * (EMB * HW) + hw;
#pragma unroll
    for (int ee = 0; ee < EMB / 4; ++ee)
        outp[(size_t)(eg + 4 * ee) * HW] = vt[p][eg + 4 * ee];

#pragma unroll
    for (int off = 16; off > 0; off >>= 1)
        s += __shfl_down_sync(0xffffffffu, s, off);
    __shared__ float ps[8];
    if ((tid & 31) == 0) ps[tid >> 5] = s;
    __syncthreads();
    if (tid < 8) {
        s = ps[tid];
#pragma unroll
        for (int off = 4; off > 0; off >>= 1)
            s += __shfl_down_sync(0xffu, s, off);
        if (tid == 0) atomicAdd(&g_loss, s);
    }
}

__global__ void k_fin(float* __restrict__ out, int full_out) {
    if (full_out)
        out[2 * N_PIX * EMB] = 12.5f * g_loss / (float)(N_PIX * EMB);
}

// ---------------------------------------------------------------------------
extern "C" void kernel_launch(void* const* d_in, const int* in_sizes, int n_in,
                              void* d_out, int out_size) {
    const float* z  = (const float*)d_in[0];
    const float* pw = (const float*)d_in[1];
    const float* pb = (const float*)d_in[2];
    const float* ew = (const float*)d_in[3];
    float* out = (float*)d_out;

    int full_out = (out_size >= 2 * N_PIX * EMB + 1 + N_PIX) ? 1 : 0;

    cudaFuncSetAttribute(k_argmax_mma, cudaFuncAttributeMaxDynamicSharedMemorySize,
                         SMEM_TOTAL);

    k_wn<<<NCODE / 256, 256>>>(ew);
    k_proj<<<N_PIX / 16, 256>>>(z, pw, pb);
    k_argmax_mma<<<N_PIX / 128, 256, SMEM_TOTAL>>>(ew);
    k_gather<<<N_PIX / 64, 256>>>(ew, out, full_out);
    k_fin<<<1, 1>>>(out, full_out);
}